// round 1
// baseline (speedup 1.0000x reference)
#include <cuda_runtime.h>
#include <math.h>

#define NN   8192
#define NE   81920
#define NE2  1310720
#define EXT  (NE2 + NE)
#define DG   64
#define HH   128
#define HSZ  (1 << 18)

// ---------------- device scratch (static, no allocation) ----------------
__device__ __align__(16) float g_f[NN * DG];
__device__ __align__(16) float g_g[NN * DG];
__device__ float g_fs[NN], g_fd[NN], g_gs[NN], g_gd[NN];
__device__ __align__(16) float g_hp[NE * DG];
__device__ float g_as[NE], g_ad[NE];
__device__ int   g_cnt[NE], g_offs[NE + 1], g_cur[NE];
__device__ int   g_srcs[EXT];
__device__ float g_eal[EXT];
__device__ float g_gate[NE], g_w[NE];
__device__ unsigned g_hkey[HSZ];
__device__ float g_hcnt[HSZ], g_hsum[HSZ];
__device__ float g_deg[NN];
__device__ int   g_cnt2[NN], g_offs2[NN + 1], g_cur2[NN];
__device__ int   g_rows2[NE];
__device__ float g_ws2[NE];
__device__ __align__(16) float g_t[NN * HH];
__device__ __align__(16) float g_h1[NN * HH];
__device__ __align__(16) float g_h2[NN * HH];
__device__ float g_gsum[HH];

// ---------------- kernels ----------------

__global__ void k_zero() {
    int i = blockIdx.x * blockDim.x + threadIdx.x;
    if (i < NE)  g_cnt[i] = 0;
    if (i < NN)  { g_cnt2[i] = 0; g_deg[i] = 0.0f; }
    if (i < HSZ) { g_hkey[i] = 0u; g_hcnt[i] = 0.0f; g_hsum[i] = 0.0f; }
    if (i < HH)  g_gsum[i] = 0.0f;
}

// f = embed @ W[0:128], g = embed @ W[128:256]; 4 nodes per 64-thread block
__global__ void k_proj(const float* __restrict__ embed, const float* __restrict__ gatW) {
    int j = threadIdx.x;            // 0..63 (output column)
    int nb = blockIdx.x * 4;
    __shared__ float se[4][128];
    for (int i = j; i < 4 * 128; i += 64) se[i / 128][i % 128] = embed[nb * 128 + i];
    __syncthreads();
    float af0 = 0, af1 = 0, af2 = 0, af3 = 0, ag0 = 0, ag1 = 0, ag2 = 0, ag3 = 0;
#pragma unroll 4
    for (int k = 0; k < 128; k++) {
        float wt = gatW[k * 64 + j];
        float wb = gatW[(k + 128) * 64 + j];
        float e0 = se[0][k], e1 = se[1][k], e2 = se[2][k], e3 = se[3][k];
        af0 += e0 * wt; af1 += e1 * wt; af2 += e2 * wt; af3 += e3 * wt;
        ag0 += e0 * wb; ag1 += e1 * wb; ag2 += e2 * wb; ag3 += e3 * wb;
    }
    g_f[(nb + 0) * 64 + j] = af0; g_f[(nb + 1) * 64 + j] = af1;
    g_f[(nb + 2) * 64 + j] = af2; g_f[(nb + 3) * 64 + j] = af3;
    g_g[(nb + 0) * 64 + j] = ag0; g_g[(nb + 1) * 64 + j] = ag1;
    g_g[(nb + 2) * 64 + j] = ag2; g_g[(nb + 3) * 64 + j] = ag3;
}

// per-node attention scalars: fs = f.att_src etc.  warp per node
__global__ void k_scal(const float* __restrict__ att_src, const float* __restrict__ att_dst) {
    int n = blockIdx.x * 8 + (threadIdx.x >> 5);
    int l = threadIdx.x & 31;
    float f0 = g_f[n * 64 + l], f1 = g_f[n * 64 + 32 + l];
    float gg0 = g_g[n * 64 + l], gg1 = g_g[n * 64 + 32 + l];
    float s0 = att_src[l], s1 = att_src[32 + l];
    float d0 = att_dst[l], d1 = att_dst[32 + l];
    float fs = f0 * s0 + f1 * s1, fd = f0 * d0 + f1 * d1;
    float gs = gg0 * s0 + gg1 * s1, gd = gg0 * d0 + gg1 * d1;
#pragma unroll
    for (int o = 16; o; o >>= 1) {
        fs += __shfl_xor_sync(0xffffffffu, fs, o);
        fd += __shfl_xor_sync(0xffffffffu, fd, o);
        gs += __shfl_xor_sync(0xffffffffu, gs, o);
        gd += __shfl_xor_sync(0xffffffffu, gd, o);
    }
    if (l == 0) { g_fs[n] = fs; g_fd[n] = fd; g_gs[n] = gs; g_gd[n] = gd; }
}

// hp[e] = f[row] + g[col]; a_s/a_d scalars; histogram edges by col for GCN CSR
__global__ void k_hp(const int* __restrict__ ei) {
    int e = blockIdx.x * 4 + (threadIdx.x >> 6);
    int j = threadIdx.x & 63;
    int r = ei[e], c = ei[NE + e];
    g_hp[e * 64 + j] = g_f[r * 64 + j] + g_g[c * 64 + j];
    if (j == 0) {
        g_as[e] = g_fs[r] + g_gs[c];
        g_ad[e] = g_fd[r] + g_gd[c];
        atomicAdd(&g_cnt2[c], 1);
    }
}

// histogram extended edges by dst
__global__ void k_hist(const int* __restrict__ ne) {
    int i = blockIdx.x * blockDim.x + threadIdx.x;
    if (i >= EXT) return;
    int dst = (i < NE2) ? ne[NE2 + i] : (i - NE2);
    atomicAdd(&g_cnt[dst], 1);
}

// single-block exclusive scan; mode 0: cnt->offs/cur (n=NE), mode 1: cnt2 (n=NN)
__global__ void k_scan(int mode) {
    const int* cnt = mode ? g_cnt2 : g_cnt;
    int* offs = mode ? g_offs2 : g_offs;
    int* cur  = mode ? g_cur2  : g_cur;
    int n = mode ? NN : NE;
    __shared__ int wsum[32];
    __shared__ int carry_s;
    int tid = threadIdx.x;
    if (tid == 0) carry_s = 0;
    __syncthreads();
    for (int base = 0; base < n; base += 1024) {
        int i = base + tid;
        int v = (i < n) ? cnt[i] : 0;
        int x = v;
#pragma unroll
        for (int o = 1; o < 32; o <<= 1) {
            int y = __shfl_up_sync(0xffffffffu, x, o);
            if ((tid & 31) >= o) x += y;
        }
        if ((tid & 31) == 31) wsum[tid >> 5] = x;
        __syncthreads();
        if (tid < 32) {
            int y = wsum[tid];
            int z = y;
#pragma unroll
            for (int o = 1; o < 32; o <<= 1) {
                int q = __shfl_up_sync(0xffffffffu, z, o);
                if (tid >= o) z += q;
            }
            wsum[tid] = z - y;   // exclusive warp offset
        }
        __syncthreads();
        int incl = x + wsum[tid >> 5];
        int carry = carry_s;
        if (i < n) { offs[i] = carry + incl - v; cur[i] = carry + incl - v; }
        __syncthreads();
        if (tid == 1023) carry_s = carry + incl;
        __syncthreads();
    }
    if (tid == 0) offs[n] = carry_s;
}

// scatter extended edges into dst-sorted order, with precomputed exp(leaky)
__global__ void k_sort1(const int* __restrict__ ne) {
    int i = blockIdx.x * blockDim.x + threadIdx.x;
    if (i >= EXT) return;
    int src, dst;
    if (i < NE2) { src = ne[i]; dst = ne[NE2 + i]; }
    else         { src = i - NE2; dst = src; }
    float a = g_as[src] + g_ad[dst];
    float alpha = (a > 0.0f) ? a : 0.2f * a;
    float eal = expf(alpha);
    int pos = atomicAdd(&g_cur[dst], 1);
    g_srcs[pos] = src;
    g_eal[pos]  = eal;
}

// warp per destination edge-node: softmax + 64-wide aggregate + Linear + gate
__global__ void k_gat(const float* __restrict__ gat_bias, const float* __restrict__ linW,
                      const float* __restrict__ lin_b, const float* __restrict__ noise,
                      const float* __restrict__ tmp) {
    int d = blockIdx.x * 8 + (threadIdx.x >> 5);
    if (d >= NE) return;
    int l = threadIdx.x & 31;
    int e0 = g_offs[d], e1 = g_offs[d + 1];
    float den = 0.0f;
    for (int i = e0 + l; i < e1; i += 32) den += g_eal[i];
#pragma unroll
    for (int o = 16; o; o >>= 1) den += __shfl_xor_sync(0xffffffffu, den, o);
    float inv = 1.0f / den;
    float a0 = 0.0f, a1 = 0.0f;
    for (int i = e0; i < e1; i++) {
        int s = g_srcs[i];
        float at = g_eal[i] * inv;
        a0 += at * g_hp[s * 64 + l];
        a1 += at * g_hp[s * 64 + 32 + l];
    }
    a0 += gat_bias[l];
    a1 += gat_bias[32 + l];
    float la = a0 * linW[l] + a1 * linW[32 + l];
#pragma unroll
    for (int o = 16; o; o >>= 1) la += __shfl_xor_sync(0xffffffffu, la, o);
    if (l == 0) {
        float nv = noise[d];
        float xv = (logf(nv) - log1pf(-nv) + la + lin_b[0]) / tmp[0];
        g_gate[d] = 1.0f / (1.0f + expf(-xv));
    }
}

__device__ __forceinline__ unsigned hash_key(unsigned key) {
    return ((key * 2654435761u) >> 14) & (HSZ - 1);
}

__global__ void k_hins(const int* __restrict__ ei) {
    int e = blockIdx.x * blockDim.x + threadIdx.x;
    if (e >= NE) return;
    unsigned key = (unsigned)ei[e] * 8192u + (unsigned)ei[NE + e] + 1u;
    unsigned s = hash_key(key);
    while (true) {
        unsigned old = atomicCAS(&g_hkey[s], 0u, key);
        if (old == 0u || old == key) break;
        s = (s + 1) & (HSZ - 1);
    }
    atomicAdd(&g_hcnt[s], 1.0f);
    atomicAdd(&g_hsum[s], g_gate[e]);
}

__device__ __forceinline__ int hash_find(unsigned key) {
    unsigned s = hash_key(key);
    while (true) {
        unsigned k = g_hkey[s];
        if (k == key) return (int)s;
        if (k == 0u) return -1;
        s = (s + 1) & (HSZ - 1);
    }
}

// edge_mask -> w, degree accumulation
__global__ void k_edgew(const int* __restrict__ ei) {
    int e = blockIdx.x * blockDim.x + threadIdx.x;
    if (e >= NE) return;
    int r = ei[e], c = ei[NE + e];
    unsigned kf = (unsigned)r * 8192u + (unsigned)c + 1u;
    unsigned kr = (unsigned)c * 8192u + (unsigned)r + 1u;
    int sf = hash_find(kf);
    float cnt = g_hcnt[sf];
    float sfw = g_hsum[sf];
    int sr = hash_find(kr);
    float srev = (sr >= 0) ? g_hsum[sr] : 0.0f;
    float em = cnt * 0.5f * (sfw + srev);
    float w = 1.0f / (1.0f + expf(-em));
    g_w[e] = w;
    atomicAdd(&g_deg[c], w);
}

// scatter original edges into col-sorted order for GCN
__global__ void k_sort2(const int* __restrict__ ei) {
    int e = blockIdx.x * blockDim.x + threadIdx.x;
    if (e >= NE) return;
    int c = ei[NE + e];
    int pos = atomicAdd(&g_cur2[c], 1);
    g_rows2[pos] = ei[e];
    g_ws2[pos]   = g_w[e];
}

// warp per node: t[n] = (xh[n] + sum_{e:col=n} w_e * xh[row_e]) / (deg[n]+1)
__global__ void k_gcn_agg(const float* __restrict__ x, int layer) {
    const float* xh = (layer == 0) ? x : ((layer == 1) ? g_h1 : g_h2);
    int n = blockIdx.x * 8 + (threadIdx.x >> 5);
    int l = threadIdx.x & 31;
    int e0 = g_offs2[n], e1 = g_offs2[n + 1];
    float4 acc = make_float4(0.f, 0.f, 0.f, 0.f);
    for (int i = e0; i < e1; i++) {
        int r = g_rows2[i];
        float w = g_ws2[i];
        float4 xr = *(const float4*)&xh[r * 128 + l * 4];
        acc.x += w * xr.x; acc.y += w * xr.y; acc.z += w * xr.z; acc.w += w * xr.w;
    }
    float invd = 1.0f / (g_deg[n] + 1.0f);
    float4 xn = *(const float4*)&xh[n * 128 + l * 4];
    float4 t;
    t.x = (xn.x + acc.x) * invd; t.y = (xn.y + acc.y) * invd;
    t.z = (xn.z + acc.z) * invd; t.w = (xn.w + acc.w) * invd;
    *(float4*)&g_t[n * 128 + l * 4] = t;
}

// out = relu(g_t @ W); 8 nodes per 128-thread block, register tiled
__global__ void k_gemm(const float* __restrict__ W, int layer) {
    float* out = (layer == 1) ? g_h2 : g_h1;
    int j = threadIdx.x;                 // 0..127 output column
    int nb = blockIdx.x * 8;
    __shared__ __align__(16) float sa[8][128];
    for (int i = j; i < 8 * 128; i += 128) sa[i / 128][i % 128] = g_t[nb * 128 + i];
    __syncthreads();
    float acc[8] = {0, 0, 0, 0, 0, 0, 0, 0};
    for (int k = 0; k < 128; k += 4) {
        float w0 = W[(k + 0) * 128 + j];
        float w1 = W[(k + 1) * 128 + j];
        float w2 = W[(k + 2) * 128 + j];
        float w3 = W[(k + 3) * 128 + j];
#pragma unroll
        for (int m = 0; m < 8; m++) {
            float4 a = *(const float4*)&sa[m][k];
            acc[m] += a.x * w0 + a.y * w1 + a.z * w2 + a.w * w3;
        }
    }
#pragma unroll
    for (int m = 0; m < 8; m++) out[(nb + m) * 128 + j] = fmaxf(acc[m], 0.0f);
}

// column sums of h3 (= g_h1 after layer 3)
__global__ void k_colmean() {
    int j = threadIdx.x;           // 0..127
    int nb = blockIdx.x * 64;
    float s = 0.0f;
    for (int m = 0; m < 64; m++) s += g_h1[(nb + m) * 128 + j];
    atomicAdd(&g_gsum[j], s);
}

__global__ void k_final(const float* __restrict__ Wc, float* __restrict__ out) {
    float l0 = 0.0f, l1 = 0.0f;
    for (int j = 0; j < 128; j++) {
        float gv = g_gsum[j] * (1.0f / 8192.0f);
        l0 += gv * Wc[j * 2 + 0];
        l1 += gv * Wc[j * 2 + 1];
    }
    float m = fmaxf(l0, l1);
    float e0 = expf(l0 - m), e1 = expf(l1 - m);
    float s = e0 + e1;
    out[0] = e0 / s;
    out[1] = e1 / s;
}

// ---------------- host launcher ----------------
extern "C" void kernel_launch(void* const* d_in, const int* in_sizes, int n_in,
                              void* d_out, int out_size) {
    const float* x        = (const float*)d_in[0];
    const float* embed    = (const float*)d_in[1];
    const float* noise    = (const float*)d_in[2];
    const float* tmp      = (const float*)d_in[3];
    const float* gatW     = (const float*)d_in[4];
    const float* att_src  = (const float*)d_in[5];
    const float* att_dst  = (const float*)d_in[6];
    const float* gat_bias = (const float*)d_in[7];
    const float* linW     = (const float*)d_in[8];
    const float* linb     = (const float*)d_in[9];
    const float* W1       = (const float*)d_in[10];
    const float* W2       = (const float*)d_in[11];
    const float* W3       = (const float*)d_in[12];
    const float* Wc       = (const float*)d_in[13];
    const int*   ei       = (const int*)d_in[14];
    const int*   ne       = (const int*)d_in[15];
    float* out = (float*)d_out;

    k_zero<<<(HSZ + 255) / 256, 256>>>();
    k_proj<<<NN / 4, 64>>>(embed, gatW);
    k_scal<<<NN / 8, 256>>>(att_src, att_dst);
    k_hp<<<NE / 4, 256>>>(ei);
    k_hist<<<(EXT + 255) / 256, 256>>>(ne);
    k_scan<<<1, 1024>>>(0);
    k_sort1<<<(EXT + 255) / 256, 256>>>(ne);
    k_gat<<<NE / 8, 256>>>(gat_bias, linW, linb, noise, tmp);
    k_hins<<<NE / 256, 256>>>(ei);
    k_edgew<<<NE / 256, 256>>>(ei);
    k_scan<<<1, 1024>>>(1);
    k_sort2<<<NE / 256, 256>>>(ei);

    k_gcn_agg<<<NN / 8, 256>>>(x, 0);
    k_gemm<<<NN / 8, 128>>>(W1, 0);
    k_gcn_agg<<<NN / 8, 256>>>(x, 1);
    k_gemm<<<NN / 8, 128>>>(W2, 1);
    k_gcn_agg<<<NN / 8, 256>>>(x, 2);
    k_gemm<<<NN / 8, 128>>>(W3, 2);

    k_colmean<<<NN / 64, 128>>>();
    k_final<<<1, 1>>>(Wc, out);
}

// round 2
// speedup vs baseline: 1.3470x; 1.3470x over previous
#include <cuda_runtime.h>
#include <math.h>

#define NN   8192
#define NE   81920
#define NE2  1310720
#define EXT  (NE2 + NE)
#define HH   128
#define HSZ  (1 << 17)

// ---------------- device scratch ----------------
__device__ __align__(16) float g_u[3][128];
__device__ __align__(16) float g_v[3][128];
__device__ __align__(16) float4 g_nf4[NN];   // (fs, fd, fq, 0) per node
__device__ __align__(16) float4 g_ng4[NN];   // (gs, gd, gq, 0) per node
__device__ __align__(16) float2 g_aa[NE];    // (a_s, a_d) per edge
__device__ __align__(16) float  g_q[NE];     // hp[e]·linW
__device__ __align__(16) int    g_cnt[NE];
__device__ __align__(16) int    g_offs[NE + 4];
__device__ int    g_cur[NE];
__device__ __align__(16) int2   g_sc[EXT];   // (src, eal bits) dst-sorted
__device__ float  g_gate[NE];
__device__ unsigned g_hkey[HSZ];
__device__ float2 g_hval[HSZ];               // (cnt, gate-sum)
__device__ float  g_deg[NN];
__device__ __align__(16) int    g_cnt2[NN];
__device__ __align__(16) int    g_offs2[NN + 4];
__device__ int    g_cur2[NN];
__device__ __align__(16) int2   g_rw[NE];    // (row, w bits) col-sorted
__device__ __align__(16) float  g_t[NN * HH];
__device__ __align__(16) float  g_h1[NN * HH];
__device__ __align__(16) float  g_h2[NN * HH];
__device__ float  g_gsum[HH];
__device__ int    g_bsum[96], g_boff[96];

// ---------------- init ----------------
__global__ void k_zero() {
    int i = blockIdx.x * blockDim.x + threadIdx.x;
    if (i < NE)  g_cnt[i] = 1;              // self-loop contributes 1 per dst
    if (i < NN)  { g_cnt2[i] = 0; g_deg[i] = 0.0f; }
    if (i < HSZ) { g_hkey[i] = 0u; g_hval[i] = make_float2(0.f, 0.f); }
    if (i < HH)  g_gsum[i] = 0.0f;
}

// u_q = W_top @ a_q, v_q = W_bot @ a_q  (a = att_src, att_dst, linW)
__global__ void k_uv(const float* __restrict__ gatW, const float* __restrict__ att_src,
                     const float* __restrict__ att_dst, const float* __restrict__ linW) {
    int t = threadIdx.x;            // 0..767
    int q = t >> 7;                 // 0..5
    int k = t & 127;
    const float* a = (q == 0 || q == 3) ? att_src : ((q == 1 || q == 4) ? att_dst : linW);
    int rb = ((q < 3) ? k : (128 + k)) * 64;
    float s = 0.0f;
#pragma unroll 8
    for (int j = 0; j < 64; j++) s += gatW[rb + j] * a[j];
    if (q < 3) g_u[q][k] = s; else g_v[q - 3][k] = s;
}

// per-node scalars: 6 dots of embed row with u/v vectors; warp per node
__global__ void k_nscal(const float* __restrict__ embed) {
    int n = blockIdx.x * 8 + (threadIdx.x >> 5);
    int l = threadIdx.x & 31;
    float4 e = *(const float4*)&embed[n * 128 + l * 4];
    float a0, a1, a2, a3, a4, a5;
    {
        float4 u;
        u = *(const float4*)&g_u[0][l * 4]; a0 = e.x*u.x + e.y*u.y + e.z*u.z + e.w*u.w;
        u = *(const float4*)&g_u[1][l * 4]; a1 = e.x*u.x + e.y*u.y + e.z*u.z + e.w*u.w;
        u = *(const float4*)&g_u[2][l * 4]; a2 = e.x*u.x + e.y*u.y + e.z*u.z + e.w*u.w;
        u = *(const float4*)&g_v[0][l * 4]; a3 = e.x*u.x + e.y*u.y + e.z*u.z + e.w*u.w;
        u = *(const float4*)&g_v[1][l * 4]; a4 = e.x*u.x + e.y*u.y + e.z*u.z + e.w*u.w;
        u = *(const float4*)&g_v[2][l * 4]; a5 = e.x*u.x + e.y*u.y + e.z*u.z + e.w*u.w;
    }
#pragma unroll
    for (int o = 16; o; o >>= 1) {
        a0 += __shfl_xor_sync(0xffffffffu, a0, o);
        a1 += __shfl_xor_sync(0xffffffffu, a1, o);
        a2 += __shfl_xor_sync(0xffffffffu, a2, o);
        a3 += __shfl_xor_sync(0xffffffffu, a3, o);
        a4 += __shfl_xor_sync(0xffffffffu, a4, o);
        a5 += __shfl_xor_sync(0xffffffffu, a5, o);
    }
    if (l == 0) {
        g_nf4[n] = make_float4(a0, a1, a2, 0.f);
        g_ng4[n] = make_float4(a3, a4, a5, 0.f);
    }
}

// per-edge scalars + col histogram
__global__ void k_edge(const int* __restrict__ ei) {
    int e = blockIdx.x * blockDim.x + threadIdx.x;
    if (e >= NE) return;
    int r = ei[e], c = ei[NE + e];
    float4 a = g_nf4[r], b = g_ng4[c];
    g_aa[e] = make_float2(a.x + b.x, a.y + b.y);
    g_q[e]  = a.z + b.z;
    atomicAdd(&g_cnt2[c], 1);
}

// histogram NE2 edges by dst (self-loops already baked into cnt init)
__global__ void k_hist(const int* __restrict__ ne) {
    int i = blockIdx.x * blockDim.x + threadIdx.x;
    if (i >= NE2) return;
    atomicAdd(&g_cnt[ne[NE2 + i]], 1);
}

// ---- hierarchical scan (mode 0: NE array, mode 1: NN array) ----
__global__ void k_blocksum(int mode) {
    const int* cnt = mode ? g_cnt2 : g_cnt;
    int t = threadIdx.x, b = blockIdx.x;
    int4 v = *(const int4*)&cnt[b * 1024 + t * 4];
    int s = v.x + v.y + v.z + v.w;
#pragma unroll
    for (int o = 16; o; o >>= 1) s += __shfl_xor_sync(0xffffffffu, s, o);
    __shared__ int ws[8];
    if ((t & 31) == 0) ws[t >> 5] = s;
    __syncthreads();
    if (t == 0) {
        int a = 0;
#pragma unroll
        for (int i = 0; i < 8; i++) a += ws[i];
        g_bsum[b] = a;
    }
}

__global__ void k_scansmall(int mode, int nb) {
    if (threadIdx.x == 0) {
        int s = 0;
        for (int i = 0; i < nb; i++) { g_boff[i] = s; s += g_bsum[i]; }
        if (mode) g_offs2[NN] = s; else g_offs[NE] = s;
    }
}

__global__ void k_blockscan(int mode) {
    const int* cnt = mode ? g_cnt2 : g_cnt;
    int* offs = mode ? g_offs2 : g_offs;
    int* cur  = mode ? g_cur2  : g_cur;
    int t = threadIdx.x, b = blockIdx.x;
    int base = b * 1024 + t * 4;
    int4 v = *(const int4*)&cnt[base];
    int s = v.x + v.y + v.z + v.w;
    int x = s;
#pragma unroll
    for (int o = 1; o < 32; o <<= 1) {
        int y = __shfl_up_sync(0xffffffffu, x, o);
        if ((t & 31) >= o) x += y;
    }
    __shared__ int ws[8], wo[8];
    if ((t & 31) == 31) ws[t >> 5] = x;
    __syncthreads();
    if (t == 0) {
        int a = 0;
#pragma unroll
        for (int i = 0; i < 8; i++) { wo[i] = a; a += ws[i]; }
    }
    __syncthreads();
    int p = x - s + wo[t >> 5] + g_boff[b];
    offs[base] = p;     cur[base] = p;     p += v.x;
    offs[base + 1] = p; cur[base + 1] = p; p += v.y;
    offs[base + 2] = p; cur[base + 2] = p; p += v.z;
    offs[base + 3] = p; cur[base + 3] = p;
}

// scatter extended edges into dst-sorted order with precomputed exp(leaky)
__global__ void k_sort1(const int* __restrict__ ne) {
    int i = blockIdx.x * blockDim.x + threadIdx.x;
    if (i >= EXT) return;
    int src, dst;
    if (i < NE2) { src = ne[i]; dst = ne[NE2 + i]; }
    else         { src = i - NE2; dst = src; }
    float a = g_aa[src].x + g_aa[dst].y;
    float alpha = (a > 0.0f) ? a : 0.2f * a;
    float eal = __expf(alpha);
    int pos = atomicAdd(&g_cur[dst], 1);
    g_sc[pos] = make_int2(src, __float_as_int(eal));
}

// 16-lane group per destination edge-node: scalar softmax-weighted sum -> gate
__global__ void k_gat(const float* __restrict__ gat_bias, const float* __restrict__ linW,
                      const float* __restrict__ lin_b, const float* __restrict__ noise,
                      const float* __restrict__ tmp) {
    int l = threadIdx.x & 31;
    int ll = l & 15;
    int d = blockIdx.x * 16 + ((threadIdx.x >> 5) << 1) + (l >> 4);
    int e0 = g_offs[d], e1 = g_offs[d + 1];
    float num = 0.0f, den = 0.0f;
    for (int i = e0 + ll; i < e1; i += 16) {
        int2 c = g_sc[i];
        float eal = __int_as_float(c.y);
        num += eal * g_q[c.x];
        den += eal;
    }
    float gb = gat_bias[ll]      * linW[ll]      + gat_bias[16 + ll] * linW[16 + ll]
             + gat_bias[32 + ll] * linW[32 + ll] + gat_bias[48 + ll] * linW[48 + ll];
#pragma unroll
    for (int o = 8; o; o >>= 1) {
        num += __shfl_xor_sync(0xffffffffu, num, o);
        den += __shfl_xor_sync(0xffffffffu, den, o);
        gb  += __shfl_xor_sync(0xffffffffu, gb, o);
    }
    if (ll == 0) {
        float la = num / den + gb + lin_b[0];
        float nv = noise[d];
        float xv = (logf(nv) - log1pf(-nv) + la) / tmp[0];
        g_gate[d] = 1.0f / (1.0f + expf(-xv));
    }
}

__device__ __forceinline__ unsigned hash_key(unsigned key) {
    return ((key * 2654435761u) >> 15) & (HSZ - 1);
}

__global__ void k_hins(const int* __restrict__ ei) {
    int e = blockIdx.x * blockDim.x + threadIdx.x;
    if (e >= NE) return;
    unsigned key = (unsigned)ei[e] * 8192u + (unsigned)ei[NE + e] + 1u;
    unsigned s = hash_key(key);
    while (true) {
        unsigned old = atomicCAS(&g_hkey[s], 0u, key);
        if (old == 0u || old == key) break;
        s = (s + 1) & (HSZ - 1);
    }
    atomicAdd(&g_hval[s].x, 1.0f);
    atomicAdd(&g_hval[s].y, g_gate[e]);
}

__device__ __forceinline__ int hash_find(unsigned key) {
    unsigned s = hash_key(key);
    while (true) {
        unsigned k = g_hkey[s];
        if (k == key) return (int)s;
        if (k == 0u) return -1;
        s = (s + 1) & (HSZ - 1);
    }
}

// fused: edge weight via hash lookups + degree + col-sorted scatter
__global__ void k_edgew_sort2(const int* __restrict__ ei) {
    int e = blockIdx.x * blockDim.x + threadIdx.x;
    if (e >= NE) return;
    int r = ei[e], c = ei[NE + e];
    int sf = hash_find((unsigned)r * 8192u + (unsigned)c + 1u);
    float2 hv = g_hval[sf];
    int sr = hash_find((unsigned)c * 8192u + (unsigned)r + 1u);
    float srev = (sr >= 0) ? g_hval[sr].y : 0.0f;
    float em = hv.x * 0.5f * (hv.y + srev);
    float w = 1.0f / (1.0f + expf(-em));
    atomicAdd(&g_deg[c], w);
    int pos = atomicAdd(&g_cur2[c], 1);
    g_rw[pos] = make_int2(r, __float_as_int(w));
}

// warp per node: t[n] = (xh[n] + sum w_e * xh[row_e]) / (deg[n]+1)
__global__ void k_gcn_agg(const float* __restrict__ x, int layer) {
    const float* xh = (layer == 0) ? x : ((layer == 1) ? g_h1 : g_h2);
    int n = blockIdx.x * 8 + (threadIdx.x >> 5);
    int l = threadIdx.x & 31;
    int e0 = g_offs2[n], e1 = g_offs2[n + 1];
    float4 acc = make_float4(0.f, 0.f, 0.f, 0.f);
    for (int i = e0; i < e1; i++) {
        int2 rw = g_rw[i];
        float w = __int_as_float(rw.y);
        float4 xr = *(const float4*)&xh[rw.x * 128 + l * 4];
        acc.x += w * xr.x; acc.y += w * xr.y; acc.z += w * xr.z; acc.w += w * xr.w;
    }
    float invd = 1.0f / (g_deg[n] + 1.0f);
    float4 xn = *(const float4*)&xh[n * 128 + l * 4];
    float4 t;
    t.x = (xn.x + acc.x) * invd; t.y = (xn.y + acc.y) * invd;
    t.z = (xn.z + acc.z) * invd; t.w = (xn.w + acc.w) * invd;
    *(float4*)&g_t[n * 128 + l * 4] = t;
}

// out = relu(g_t @ W); 16 nodes per 128-thread block; layer 2 accumulates mean-pool
__global__ void k_gemm(const float* __restrict__ W, int layer) {
    int j = threadIdx.x;
    int nb = blockIdx.x * 16;
    __shared__ __align__(16) float sa[16][128];
    {
        const float4* src = (const float4*)&g_t[nb * 128];
        float4* dst = (float4*)sa;
        for (int i = j; i < 16 * 32; i += 128) dst[i] = src[i];
    }
    __syncthreads();
    float acc[16] = {};
    for (int k = 0; k < 128; k += 4) {
        float w0 = W[(k + 0) * 128 + j];
        float w1 = W[(k + 1) * 128 + j];
        float w2 = W[(k + 2) * 128 + j];
        float w3 = W[(k + 3) * 128 + j];
#pragma unroll
        for (int m = 0; m < 16; m++) {
            float4 a = *(const float4*)&sa[m][k];
            acc[m] += a.x * w0 + a.y * w1 + a.z * w2 + a.w * w3;
        }
    }
    if (layer == 2) {
        float s = 0.0f;
#pragma unroll
        for (int m = 0; m < 16; m++) s += fmaxf(acc[m], 0.0f);
        atomicAdd(&g_gsum[j], s);
    } else {
        float* out = layer ? g_h2 : g_h1;
#pragma unroll
        for (int m = 0; m < 16; m++) out[(nb + m) * 128 + j] = fmaxf(acc[m], 0.0f);
    }
}

__global__ void k_final(const float* __restrict__ Wc, float* __restrict__ out) {
    int l = threadIdx.x;
    float l0 = 0.0f, l1 = 0.0f;
    for (int j = l; j < 128; j += 32) {
        float gv = g_gsum[j] * (1.0f / 8192.0f);
        l0 += gv * Wc[j * 2 + 0];
        l1 += gv * Wc[j * 2 + 1];
    }
#pragma unroll
    for (int o = 16; o; o >>= 1) {
        l0 += __shfl_xor_sync(0xffffffffu, l0, o);
        l1 += __shfl_xor_sync(0xffffffffu, l1, o);
    }
    if (l == 0) {
        float m = fmaxf(l0, l1);
        float e0 = expf(l0 - m), e1 = expf(l1 - m);
        float s = e0 + e1;
        out[0] = e0 / s;
        out[1] = e1 / s;
    }
}

// ---------------- host launcher ----------------
extern "C" void kernel_launch(void* const* d_in, const int* in_sizes, int n_in,
                              void* d_out, int out_size) {
    const float* x        = (const float*)d_in[0];
    const float* embed    = (const float*)d_in[1];
    const float* noise    = (const float*)d_in[2];
    const float* tmp      = (const float*)d_in[3];
    const float* gatW     = (const float*)d_in[4];
    const float* att_src  = (const float*)d_in[5];
    const float* att_dst  = (const float*)d_in[6];
    const float* gat_bias = (const float*)d_in[7];
    const float* linW     = (const float*)d_in[8];
    const float* linb     = (const float*)d_in[9];
    const float* W1       = (const float*)d_in[10];
    const float* W2       = (const float*)d_in[11];
    const float* W3       = (const float*)d_in[12];
    const float* Wc       = (const float*)d_in[13];
    const int*   ei       = (const int*)d_in[14];
    const int*   ne       = (const int*)d_in[15];
    float* out = (float*)d_out;

    k_zero<<<HSZ / 256, 256>>>();
    k_uv<<<1, 768>>>(gatW, att_src, att_dst, linW);
    k_nscal<<<NN / 8, 256>>>(embed);
    k_edge<<<NE / 256, 256>>>(ei);
    k_hist<<<NE2 / 256, 256>>>(ne);
    k_blocksum<<<NE / 1024, 256>>>(0);
    k_scansmall<<<1, 32>>>(0, NE / 1024);
    k_blockscan<<<NE / 1024, 256>>>(0);
    k_sort1<<<EXT / 256, 256>>>(ne);
    k_gat<<<NE / 16, 256>>>(gat_bias, linW, linb, noise, tmp);
    k_hins<<<NE / 256, 256>>>(ei);
    k_blocksum<<<NN / 1024, 256>>>(1);
    k_scansmall<<<1, 32>>>(1, NN / 1024);
    k_blockscan<<<NN / 1024, 256>>>(1);
    k_edgew_sort2<<<NE / 256, 256>>>(ei);

    k_gcn_agg<<<NN / 8, 256>>>(x, 0);
    k_gemm<<<NN / 16, 128>>>(W1, 0);
    k_gcn_agg<<<NN / 8, 256>>>(x, 1);
    k_gemm<<<NN / 16, 128>>>(W2, 1);
    k_gcn_agg<<<NN / 8, 256>>>(x, 2);
    k_gemm<<<NN / 16, 128>>>(W3, 2);

    k_final<<<1, 32>>>(Wc, out);
}

// round 3
// speedup vs baseline: 1.8771x; 1.3935x over previous
#include <cuda_runtime.h>
#include <math.h>

#define NN   8192
#define NE   81920
#define NE2  1310720
#define HH   128
#define HSZ  (1 << 18)

// ---------------- device scratch ----------------
__device__ __align__(16) float g_u[3][128];
__device__ __align__(16) float g_v[3][128];
__device__ float  g_gb;                      // gat_bias . linW
__device__ __align__(16) float4 g_nf4[NN];   // (fs, fd, fq, 0) per node
__device__ __align__(16) float4 g_ng4[NN];   // (gs, gd, gq, 0) per node
__device__ __align__(16) float4 g_aq[NE];    // (a_s, a_d, q, 0) per edge
__device__ float  g_adst[NE];                // a_d copy (dst gather)
__device__ __align__(16) float2 g_numden[NE];
__device__ unsigned g_hkey[HSZ];
__device__ __align__(16) float2 g_hval[HSZ]; // (cnt, gate-sum)
__device__ float  g_deg[NN];
__device__ __align__(16) int    g_cnt2[NN];
__device__ int    g_offs2[NN + 1];
__device__ int    g_cur2[NN];
__device__ __align__(16) int2   g_rw[NE];    // (row, w bits) col-sorted
__device__ __align__(16) float  g_h1[NN * HH];
__device__ __align__(16) float  g_h2[NN * HH];
__device__ float  g_gsum[HH];

// ---------------- init ----------------
__global__ void k_zero() {
    int i = blockIdx.x * blockDim.x + threadIdx.x;
    if (i < HSZ) { g_hkey[i] = 0u; g_hval[i] = make_float2(0.f, 0.f); }
    if (i < NN)  { g_cnt2[i] = 0; g_deg[i] = 0.0f; }
    if (i < HH)  g_gsum[i] = 0.0f;
}

// u_q = W_top @ a_q, v_q = W_bot @ a_q  (a = att_src, att_dst, linW); also gb scalar
__global__ void k_uv(const float* __restrict__ gatW, const float* __restrict__ att_src,
                     const float* __restrict__ att_dst, const float* __restrict__ linW,
                     const float* __restrict__ gat_bias) {
    int t = threadIdx.x;            // 0..767
    int q = t >> 7;                 // 0..5
    int k = t & 127;
    const float* a = (q == 0 || q == 3) ? att_src : ((q == 1 || q == 4) ? att_dst : linW);
    int rb = ((q < 3) ? k : (128 + k)) * 64;
    float s = 0.0f;
#pragma unroll 8
    for (int j = 0; j < 64; j++) s += gatW[rb + j] * a[j];
    if (q < 3) g_u[q][k] = s; else g_v[q - 3][k] = s;
    if (t < 32) {
        float gb = gat_bias[t] * linW[t] + gat_bias[t + 32] * linW[t + 32];
#pragma unroll
        for (int o = 16; o; o >>= 1) gb += __shfl_xor_sync(0xffffffffu, gb, o);
        if (t == 0) g_gb = gb;
    }
}

// per-node scalars: 6 dots of embed row with u/v vectors; warp per node
__global__ void k_nscal(const float* __restrict__ embed) {
    int n = blockIdx.x * 8 + (threadIdx.x >> 5);
    int l = threadIdx.x & 31;
    float4 e = *(const float4*)&embed[n * 128 + l * 4];
    float a0, a1, a2, a3, a4, a5;
    {
        float4 u;
        u = *(const float4*)&g_u[0][l * 4]; a0 = e.x*u.x + e.y*u.y + e.z*u.z + e.w*u.w;
        u = *(const float4*)&g_u[1][l * 4]; a1 = e.x*u.x + e.y*u.y + e.z*u.z + e.w*u.w;
        u = *(const float4*)&g_u[2][l * 4]; a2 = e.x*u.x + e.y*u.y + e.z*u.z + e.w*u.w;
        u = *(const float4*)&g_v[0][l * 4]; a3 = e.x*u.x + e.y*u.y + e.z*u.z + e.w*u.w;
        u = *(const float4*)&g_v[1][l * 4]; a4 = e.x*u.x + e.y*u.y + e.z*u.z + e.w*u.w;
        u = *(const float4*)&g_v[2][l * 4]; a5 = e.x*u.x + e.y*u.y + e.z*u.z + e.w*u.w;
    }
#pragma unroll
    for (int o = 16; o; o >>= 1) {
        a0 += __shfl_xor_sync(0xffffffffu, a0, o);
        a1 += __shfl_xor_sync(0xffffffffu, a1, o);
        a2 += __shfl_xor_sync(0xffffffffu, a2, o);
        a3 += __shfl_xor_sync(0xffffffffu, a3, o);
        a4 += __shfl_xor_sync(0xffffffffu, a4, o);
        a5 += __shfl_xor_sync(0xffffffffu, a5, o);
    }
    if (l == 0) {
        g_nf4[n] = make_float4(a0, a1, a2, 0.f);
        g_ng4[n] = make_float4(a3, a4, a5, 0.f);
    }
}

// per-edge scalars + numden self-loop init + col histogram
__global__ void k_edge(const int* __restrict__ ei) {
    int e = blockIdx.x * blockDim.x + threadIdx.x;
    if (e >= NE) return;
    int r = ei[e], c = ei[NE + e];
    float4 a = g_nf4[r], b = g_ng4[c];
    float as = a.x + b.x, ad = a.y + b.y, q = a.z + b.z;
    g_aq[e]   = make_float4(as, ad, q, 0.f);
    g_adst[e] = ad;
    float al = as + ad;
    al = (al > 0.0f) ? al : 0.2f * al;
    float eal = __expf(al);
    g_numden[e] = make_float2(eal * q, eal);   // self-loop contribution
    atomicAdd(&g_cnt2[c], 1);
}

// one float2 atomic per extended edge: segmented (num, den) sums by dst
__global__ void k_scatter(const int* __restrict__ ne) {
    int i = blockIdx.x * blockDim.x + threadIdx.x;
    int j = i + NE2 / 2;
    int s0 = ne[i],        d0 = ne[NE2 + i];
    int s1 = ne[j],        d1 = ne[NE2 + j];
    float4 aq0 = g_aq[s0];
    float4 aq1 = g_aq[s1];
    float  b0  = g_adst[d0];
    float  b1  = g_adst[d1];
    float a0 = aq0.x + b0; a0 = (a0 > 0.0f) ? a0 : 0.2f * a0;
    float a1 = aq1.x + b1; a1 = (a1 > 0.0f) ? a1 : 0.2f * a1;
    float e0 = __expf(a0), e1 = __expf(a1);
    atomicAdd(&g_numden[d0], make_float2(e0 * aq0.z, e0));
    atomicAdd(&g_numden[d1], make_float2(e1 * aq1.z, e1));
}

__device__ __forceinline__ unsigned hash_key(unsigned key) {
    return ((key * 2654435761u) >> 14) & (HSZ - 1);
}

// fused: gate computation + hash insert
__global__ void k_hins(const int* __restrict__ ei, const float* __restrict__ noise,
                       const float* __restrict__ tmp, const float* __restrict__ linb) {
    int e = blockIdx.x * blockDim.x + threadIdx.x;
    if (e >= NE) return;
    float2 nd = g_numden[e];
    float la = nd.x / nd.y + g_gb + linb[0];
    float nv = noise[e];
    float xv = (logf(nv) - log1pf(-nv) + la) / tmp[0];
    float gate = 1.0f / (1.0f + expf(-xv));
    unsigned key = (unsigned)ei[e] * 8192u + (unsigned)ei[NE + e] + 1u;
    unsigned s = hash_key(key);
    while (true) {
        unsigned old = atomicCAS(&g_hkey[s], 0u, key);
        if (old == 0u || old == key) break;
        s = (s + 1) & (HSZ - 1);
    }
    atomicAdd(&g_hval[s], make_float2(1.0f, gate));
}

__device__ __forceinline__ int hash_find(unsigned key) {
    unsigned s = hash_key(key);
    while (true) {
        unsigned k = g_hkey[s];
        if (k == key) return (int)s;
        if (k == 0u) return -1;
        s = (s + 1) & (HSZ - 1);
    }
}

// single-block scan of g_cnt2[8192] -> offs2/cur2
__global__ void k_scan2() {
    int t = threadIdx.x;
    int base = t * 8;
    int4 v0 = *(const int4*)&g_cnt2[base];
    int4 v1 = *(const int4*)&g_cnt2[base + 4];
    int vals[8] = {v0.x, v0.y, v0.z, v0.w, v1.x, v1.y, v1.z, v1.w};
    int s = 0;
#pragma unroll
    for (int k = 0; k < 8; k++) s += vals[k];
    int x = s;
#pragma unroll
    for (int o = 1; o < 32; o <<= 1) {
        int y = __shfl_up_sync(0xffffffffu, x, o);
        if ((t & 31) >= o) x += y;
    }
    __shared__ int ws[32], wo[32];
    if ((t & 31) == 31) ws[t >> 5] = x;
    __syncthreads();
    if (t < 32) {
        int y = ws[t];
        int z = y;
#pragma unroll
        for (int o = 1; o < 32; o <<= 1) {
            int q = __shfl_up_sync(0xffffffffu, z, o);
            if (t >= o) z += q;
        }
        wo[t] = z - y;
    }
    __syncthreads();
    int p = (x - s) + wo[t >> 5];
#pragma unroll
    for (int k = 0; k < 8; k++) {
        g_offs2[base + k] = p;
        g_cur2[base + k]  = p;
        p += vals[k];
    }
    if (t == 1023) g_offs2[NN] = p;
}

// fused: edge weight via hash lookups + degree + col-sorted scatter
__global__ void k_edgew_sort2(const int* __restrict__ ei) {
    int e = blockIdx.x * blockDim.x + threadIdx.x;
    if (e >= NE) return;
    int r = ei[e], c = ei[NE + e];
    int sf = hash_find((unsigned)r * 8192u + (unsigned)c + 1u);
    float2 hv = g_hval[sf];
    int sr = hash_find((unsigned)c * 8192u + (unsigned)r + 1u);
    float srev = (sr >= 0) ? g_hval[sr].y : 0.0f;
    float em = hv.x * 0.5f * (hv.y + srev);
    float w = 1.0f / (1.0f + expf(-em));
    atomicAdd(&g_deg[c], w);
    int pos = atomicAdd(&g_cur2[c], 1);
    g_rw[pos] = make_int2(r, __float_as_int(w));
}

// fused GCN layer: aggregate (warp per 2 nodes -> smem) then GEMM (+relu)
__global__ void k_gcn(const float* __restrict__ xin, const float* __restrict__ W, int layer) {
    const float* xh = (layer == 0) ? xin : ((layer == 1) ? g_h1 : g_h2);
    int nb = blockIdx.x * 16;
    __shared__ __align__(16) float sa[16][128];
    int wid = threadIdx.x >> 5, l = threadIdx.x & 31;
#pragma unroll
    for (int mm = 0; mm < 2; mm++) {
        int m = wid * 2 + mm;
        int n = nb + m;
        int e0 = g_offs2[n], e1 = g_offs2[n + 1];
        float4 acc = make_float4(0.f, 0.f, 0.f, 0.f);
        for (int i = e0; i < e1; i++) {
            int2 rw = g_rw[i];
            float wt = __int_as_float(rw.y);
            float4 xr = *(const float4*)&xh[rw.x * 128 + l * 4];
            acc.x += wt * xr.x; acc.y += wt * xr.y; acc.z += wt * xr.z; acc.w += wt * xr.w;
        }
        float invd = 1.0f / (g_deg[n] + 1.0f);
        float4 xn = *(const float4*)&xh[n * 128 + l * 4];
        float4 t;
        t.x = (xn.x + acc.x) * invd; t.y = (xn.y + acc.y) * invd;
        t.z = (xn.z + acc.z) * invd; t.w = (xn.w + acc.w) * invd;
        *(float4*)&sa[m][l * 4] = t;
    }
    __syncthreads();
    int j = threadIdx.x & 127;
    int half = threadIdx.x >> 7;
    float acc[8] = {};
    for (int k = 0; k < 128; k += 4) {
        float w0 = W[(k + 0) * 128 + j];
        float w1 = W[(k + 1) * 128 + j];
        float w2 = W[(k + 2) * 128 + j];
        float w3 = W[(k + 3) * 128 + j];
#pragma unroll
        for (int m = 0; m < 8; m++) {
            float4 a = *(const float4*)&sa[half * 8 + m][k];
            acc[m] += a.x * w0 + a.y * w1 + a.z * w2 + a.w * w3;
        }
    }
    if (layer == 2) {
        float s = 0.0f;
#pragma unroll
        for (int m = 0; m < 8; m++) s += fmaxf(acc[m], 0.0f);
        atomicAdd(&g_gsum[j], s);
    } else {
        float* out = layer ? g_h2 : g_h1;
#pragma unroll
        for (int m = 0; m < 8; m++) out[(nb + half * 8 + m) * 128 + j] = fmaxf(acc[m], 0.0f);
    }
}

__global__ void k_final(const float* __restrict__ Wc, float* __restrict__ out) {
    int l = threadIdx.x;
    float l0 = 0.0f, l1 = 0.0f;
    for (int j = l; j < 128; j += 32) {
        float gv = g_gsum[j] * (1.0f / 8192.0f);
        l0 += gv * Wc[j * 2 + 0];
        l1 += gv * Wc[j * 2 + 1];
    }
#pragma unroll
    for (int o = 16; o; o >>= 1) {
        l0 += __shfl_xor_sync(0xffffffffu, l0, o);
        l1 += __shfl_xor_sync(0xffffffffu, l1, o);
    }
    if (l == 0) {
        float m = fmaxf(l0, l1);
        float e0 = expf(l0 - m), e1 = expf(l1 - m);
        float s = e0 + e1;
        out[0] = e0 / s;
        out[1] = e1 / s;
    }
}

// ---------------- host launcher ----------------
extern "C" void kernel_launch(void* const* d_in, const int* in_sizes, int n_in,
                              void* d_out, int out_size) {
    const float* x        = (const float*)d_in[0];
    const float* embed    = (const float*)d_in[1];
    const float* noise    = (const float*)d_in[2];
    const float* tmp      = (const float*)d_in[3];
    const float* gatW     = (const float*)d_in[4];
    const float* att_src  = (const float*)d_in[5];
    const float* att_dst  = (const float*)d_in[6];
    const float* gat_bias = (const float*)d_in[7];
    const float* linW     = (const float*)d_in[8];
    const float* linb     = (const float*)d_in[9];
    const float* W1       = (const float*)d_in[10];
    const float* W2       = (const float*)d_in[11];
    const float* W3       = (const float*)d_in[12];
    const float* Wc       = (const float*)d_in[13];
    const int*   ei       = (const int*)d_in[14];
    const int*   ne       = (const int*)d_in[15];
    float* out = (float*)d_out;

    k_zero<<<HSZ / 256, 256>>>();
    k_uv<<<1, 768>>>(gatW, att_src, att_dst, linW, gat_bias);
    k_nscal<<<NN / 8, 256>>>(embed);
    k_edge<<<NE / 256, 256>>>(ei);
    k_scatter<<<NE2 / 512, 256>>>(ne);
    k_hins<<<NE / 256, 256>>>(ei, noise, tmp, linb);
    k_scan2<<<1, 1024>>>();
    k_edgew_sort2<<<NE / 256, 256>>>(ei);

    k_gcn<<<NN / 16, 256>>>(x, W1, 0);
    k_gcn<<<NN / 16, 256>>>(x, W2, 1);
    k_gcn<<<NN / 16, 256>>>(x, W3, 2);

    k_final<<<1, 32>>>(Wc, out);
}